// round 1
// baseline (speedup 1.0000x reference)
#include <cuda_runtime.h>

// HONU degree-3: out[r] = sum_{a<=b<=c} w(a,b,c) * xs[a][r]*xs[b][r]*xs[c][r]
// xs[0][r] = 1 (bias), xs[f][r] = x[r][f-1].
// Weight index of combo (a,b,c) is its lexicographic rank (closed form) — the
// comb_idx input is redundant and ignored.
//
// Decomposition: for fixed pair (a,b), weights of the c-run are contiguous:
//   s_ab[r] = sum_c w[base(a,b)+(c-b)] * xs[c][r];  out[r] += xs[a][r]*xs[b][r]*s_ab[r]
// We block 8 consecutive 'a' streams per (b, octet) so one xs[c] load feeds 8 FMAs,
// and use Blackwell packed fma.rn.f32x2 (2 rows per instr). Each warp is one
// worker handling all 256 rows (8 rows/thread as 2 float4 quads).

#define NFEAT 129
#define NROW  256
#define NBLK  152
#define WPB   8                 // warps (= workers) per block
#define NWORK (NBLK * WPB)      // 1216 workers

__host__ __device__ __forceinline__ int c2i(int x) { return x * (x - 1) / 2; }
__host__ __device__ __forceinline__ int c3i(int x) { return x * (x - 1) * (x - 2) / 6; }

// flat lexicographic rank of combo (a, b, b): 366145 = C(131,3)
__device__ __forceinline__ int comb_base(int a, int b) {
    return 366145 - c3i(131 - a) + c2i(130 - a) - c2i(130 - b);
}

// total blocked iterations: sum_b ceil((b+1)/8) * (129-b)
constexpr long long blocked_total() {
    long long t = 0;
    for (int b = 0; b < NFEAT; b++) t += (long long)((b + 8) / 8) * (NFEAT - b);
    return t;
}
constexpr long long T_TOTAL = blocked_total();

__device__ float g_partial[NBLK * NROW];

__device__ __forceinline__ unsigned long long pack2(float w) {
    unsigned long long r;
    unsigned int wi = __float_as_uint(w);
    asm("mov.b64 %0, {%1, %1};" : "=l"(r) : "r"(wi));
    return r;
}
__device__ __forceinline__ void fma2(unsigned long long& d, unsigned long long a,
                                     unsigned long long b) {
    asm("fma.rn.f32x2 %0, %1, %2, %0;" : "+l"(d) : "l"(a), "l"(b));
}
__device__ __forceinline__ unsigned long long mul2(unsigned long long a,
                                                   unsigned long long b) {
    unsigned long long d;
    asm("mul.rn.f32x2 %0, %1, %2;" : "=l"(d) : "l"(a), "l"(b));
    return d;
}

__global__ void __launch_bounds__(256, 1)
honu_main(const float* __restrict__ x, const float* __restrict__ w) {
    extern __shared__ float smem[];
    float* xs   = smem;                   // [129][256] feature-major
    float* obuf = smem + NFEAT * NROW;    // [8][256] per-warp partials

    int tid = threadIdx.x;

    // ---- prologue: load x transposed into smem (thread t owns row t) ----
    {
        const float4* xg = (const float4*)(x + (size_t)tid * 128);
#pragma unroll
        for (int k = 0; k < 32; k++) {
            float4 v = xg[k];
            xs[(4 * k + 1) * NROW + tid] = v.x;
            xs[(4 * k + 2) * NROW + tid] = v.y;
            xs[(4 * k + 3) * NROW + tid] = v.z;
            xs[(4 * k + 4) * NROW + tid] = v.w;
        }
        xs[tid] = 1.0f;  // bias feature
    }
    __syncthreads();

    int warp = tid >> 5, lane = tid & 31;
    int worker = blockIdx.x * WPB + warp;

    long long s = (T_TOTAL * worker) / NWORK;
    long long e = (T_TOTAL * (worker + 1)) / NWORK;

    // decode start position -> (b, octet o, c-offset)
    int b = 0;
    long long pref = 0;
    for (;;) {
        long long nb = pref + (long long)((b + 8) >> 3) * (NFEAT - b);
        if (nb > s) break;
        pref = nb;
        b++;
    }
    int L = NFEAT - b;
    int rem = (int)(s - pref);
    int o = rem / L;
    int coff = rem % L;
    long long pos = s;

    unsigned long long ov0 = 0, ov1 = 0, ov2 = 0, ov3 = 0;  // out accum (8 rows as 4x f32x2)

    const ulonglong2* xs2 = (const ulonglong2*)xs;  // 64 quads (of 4 floats) per feature
    const int l0 = lane, l1 = lane + 32;

    while (pos < e) {
        L = NFEAT - b;
        int a0 = o << 3;
        int na = b + 1 - a0;
        if (na > 8) na = 8;
        int seg = L - coff;
        if (seg > (int)(e - pos)) seg = (int)(e - pos);
        int c0 = b + coff;

        const float* wp[8];
#pragma unroll
        for (int j = 0; j < 8; j++)
            wp[j] = w + ((j < na) ? (comb_base(a0 + j, b) + coff) : 0);

        unsigned long long acc[8][4];
#pragma unroll
        for (int j = 0; j < 8; j++) {
            acc[j][0] = 0; acc[j][1] = 0; acc[j][2] = 0; acc[j][3] = 0;
        }

        if (na == 8) {
            for (int cc = 0; cc < seg; ++cc) {
                const ulonglong2* xp = xs2 + (size_t)(c0 + cc) * 64;
                ulonglong2 xv0 = xp[l0];
                ulonglong2 xv1 = xp[l1];
#pragma unroll
                for (int j = 0; j < 8; j++) {
                    unsigned long long w2 = pack2(__ldg(wp[j] + cc));
                    fma2(acc[j][0], w2, xv0.x);
                    fma2(acc[j][1], w2, xv0.y);
                    fma2(acc[j][2], w2, xv1.x);
                    fma2(acc[j][3], w2, xv1.y);
                }
            }
        } else {
            for (int cc = 0; cc < seg; ++cc) {
                const ulonglong2* xp = xs2 + (size_t)(c0 + cc) * 64;
                ulonglong2 xv0 = xp[l0];
                ulonglong2 xv1 = xp[l1];
#pragma unroll
                for (int j = 0; j < 8; j++) {
                    if (j < na) {
                        unsigned long long w2 = pack2(__ldg(wp[j] + cc));
                        fma2(acc[j][0], w2, xv0.x);
                        fma2(acc[j][1], w2, xv0.y);
                        fma2(acc[j][2], w2, xv1.x);
                        fma2(acc[j][3], w2, xv1.y);
                    }
                }
            }
        }

        // epilogue: out += (x_a * x_b) * s_ab   (linearity allows partial c-runs)
        {
            const ulonglong2* xbp = xs2 + (size_t)b * 64;
            ulonglong2 xb0 = xbp[l0];
            ulonglong2 xb1 = xbp[l1];
#pragma unroll
            for (int j = 0; j < 8; j++) {
                if (j < na) {
                    const ulonglong2* xap = xs2 + (size_t)(a0 + j) * 64;
                    ulonglong2 xa0 = xap[l0];
                    ulonglong2 xa1 = xap[l1];
                    fma2(ov0, mul2(xa0.x, xb0.x), acc[j][0]);
                    fma2(ov1, mul2(xa0.y, xb0.y), acc[j][1]);
                    fma2(ov2, mul2(xa1.x, xb1.x), acc[j][2]);
                    fma2(ov3, mul2(xa1.y, xb1.y), acc[j][3]);
                }
            }
        }

        pos += seg;
        coff += seg;
        if (coff == L) {
            coff = 0;
            o++;
            if ((o << 3) > b) { o = 0; b++; }
        }
    }

    // ---- per-warp partials -> smem, block combine -> global partial ----
    {
        float4* ob = (float4*)(obuf + warp * NROW);
        union { unsigned long long q[2]; float4 f; } u;
        u.q[0] = ov0; u.q[1] = ov1;
        ob[lane] = u.f;           // rows 4*lane .. 4*lane+3
        u.q[0] = ov2; u.q[1] = ov3;
        ob[lane + 32] = u.f;      // rows 128+4*lane ..
    }
    __syncthreads();
    {
        float ssum = 0.0f;
#pragma unroll
        for (int i = 0; i < WPB; i++) ssum += obuf[i * NROW + tid];
        g_partial[blockIdx.x * NROW + tid] = ssum;
    }
}

__global__ void __launch_bounds__(256, 1) honu_reduce(float* __restrict__ out) {
    int r = threadIdx.x;
    float ssum = 0.0f;
#pragma unroll 8
    for (int i = 0; i < NBLK; i++) ssum += g_partial[i * NROW + r];
    out[r] = ssum;
}

extern "C" void kernel_launch(void* const* d_in, const int* in_sizes, int n_in,
                              void* d_out, int out_size) {
    (void)in_sizes; (void)n_in; (void)out_size;
    const float* x = (const float*)d_in[0];
    const float* w = (const float*)d_in[1];
    // d_in[2] (comb_idx) intentionally unused: lexicographic rank is closed-form.

    size_t smem_bytes = (size_t)(NFEAT * NROW + WPB * NROW) * sizeof(float);  // 140,288 B
    cudaFuncSetAttribute(honu_main, cudaFuncAttributeMaxDynamicSharedMemorySize,
                         (int)smem_bytes);
    honu_main<<<NBLK, 256, smem_bytes>>>(x, w);
    honu_reduce<<<1, 256>>>((float*)d_out);
}

// round 4
// speedup vs baseline: 1.0440x; 1.0440x over previous
#include <cuda_runtime.h>

// HONU degree-3: out[r] = sum_{a<=b<=c} w(a,b,c) * xs[a][r]*xs[b][r]*xs[c][r]
// xs[0][r] = 1 (bias), xs[f][r] = x[r][f-1].
// Weight index of combo (a,b,c) = lexicographic rank (closed form); comb_idx
// input is redundant and ignored.
//
// Pair factorization: for fixed (a,b), the c-run weights are contiguous:
//   s_ab[r] = sum_c w[base(a,b)+(c-b)] * xs[c][r];  out[r] += xs[a][r]*xs[b][r]*s_ab[r]
// 8 consecutive 'a' streams share each xs[c] load; rows processed 8/thread as
// packed fma.rn.f32x2. Weights fetched in quads of 4 c-steps with 1-quad
// software prefetch (32 independent LDGs in flight per quad).
// Grid = 148 (exactly 1 wave, 1 block/SM). Final cross-block reduction fused
// via threadfence + atomic ticket (last block reduces; counter self-resets).

#define NFEAT 129
#define NROW  256
#define NBLK  148
#define WPB   8
#define NWORK (NBLK * WPB)   // 1184 workers

__host__ __device__ __forceinline__ int c2i(int v) { return v * (v - 1) / 2; }
__host__ __device__ __forceinline__ int c3i(int v) { return v * (v - 1) * (v - 2) / 6; }

// flat lexicographic rank of combo (a, b, b); total combos = C(131,3) = 366145
__device__ __forceinline__ int comb_base(int a, int b) {
    return 366145 - c3i(131 - a) + c2i(130 - a) - c2i(130 - b);
}

// total blocked iterations: sum_b ceil((b+1)/8) * (129-b)
constexpr long long blocked_total() {
    long long t = 0;
    for (int b = 0; b < NFEAT; b++) t += (long long)((b + 8) / 8) * (NFEAT - b);
    return t;
}
constexpr long long T_TOTAL = blocked_total();

__device__ float g_partial[NBLK * NROW];
__device__ int   g_count = 0;

__device__ __forceinline__ unsigned long long pack2(float w) {
    unsigned long long r;
    unsigned int wi = __float_as_uint(w);
    asm("mov.b64 %0, {%1, %1};" : "=l"(r) : "r"(wi));
    return r;
}
__device__ __forceinline__ void fma2(unsigned long long& d, unsigned long long a,
                                     unsigned long long b) {
    asm("fma.rn.f32x2 %0, %1, %2, %0;" : "+l"(d) : "l"(a), "l"(b));
}
__device__ __forceinline__ unsigned long long mul2(unsigned long long a,
                                                   unsigned long long b) {
    unsigned long long d;
    asm("mul.rn.f32x2 %0, %1, %2;" : "=l"(d) : "l"(a), "l"(b));
    return d;
}

__global__ void __launch_bounds__(256, 1)
honu_main(const float* __restrict__ x, const float* __restrict__ w,
          float* __restrict__ out) {
    extern __shared__ float smem[];
    float* xs   = smem;                   // [129][256] feature-major
    float* obuf = smem + NFEAT * NROW;    // [8][256] per-warp partials

    int tid = threadIdx.x;

    // ---- prologue: x transposed into smem (thread t owns row t) ----
    {
        const float4* xg = (const float4*)(x + (size_t)tid * 128);
#pragma unroll
        for (int k = 0; k < 32; k++) {
            float4 v = xg[k];
            xs[(4 * k + 1) * NROW + tid] = v.x;
            xs[(4 * k + 2) * NROW + tid] = v.y;
            xs[(4 * k + 3) * NROW + tid] = v.z;
            xs[(4 * k + 4) * NROW + tid] = v.w;
        }
        xs[tid] = 1.0f;  // bias feature
    }
    __syncthreads();

    int warp = tid >> 5, lane = tid & 31;
    int worker = blockIdx.x * WPB + warp;

    long long s = (T_TOTAL * worker) / NWORK;
    long long e = (T_TOTAL * (worker + 1)) / NWORK;

    // decode start -> (b, octet o, c-offset)
    int b = 0;
    long long pref = 0;
    for (;;) {
        long long nb = pref + (long long)((b + 8) >> 3) * (NFEAT - b);
        if (nb > s) break;
        pref = nb;
        b++;
    }
    int L = NFEAT - b;
    int rem = (int)(s - pref);
    int o = rem / L;
    int coff = rem % L;
    long long pos = s;

    unsigned long long ov0 = 0, ov1 = 0, ov2 = 0, ov3 = 0;  // 8 rows as 4x f32x2

    const ulonglong2* xs2 = (const ulonglong2*)xs;  // 64 16B-quads per feature
    const int l0 = lane, l1 = lane + 32;

    while (pos < e) {
        L = NFEAT - b;
        int a0 = o << 3;
        int na = b + 1 - a0;
        if (na > 8) na = 8;
        int seg = L - coff;
        if (seg > (int)(e - pos)) seg = (int)(e - pos);
        int c0 = b + coff;

        unsigned int woff[8];
#pragma unroll
        for (int j = 0; j < 8; j++)
            woff[j] = (unsigned int)((j < na) ? (comb_base(a0 + j, b) + coff) : 0);

        unsigned long long acc[8][4];
#pragma unroll
        for (int j = 0; j < 8; j++) {
            acc[j][0] = 0; acc[j][1] = 0; acc[j][2] = 0; acc[j][3] = 0;
        }

        // ---- c loop in quads of 4 with 1-quad prefetch ----
        // loads are clamped to the stream length L (always in-bounds);
        // accumulation is masked by seg.
        int maxi = L - 1 - coff;      // max valid cc offset for loads
        float wc[8][4];
#pragma unroll
        for (int u = 0; u < 4; u++) {
            int idx = (u < maxi) ? u : maxi;
#pragma unroll
            for (int j = 0; j < 8; j++) wc[j][u] = __ldg(w + woff[j] + idx);
        }

        int full = seg & ~3;
        for (int q = 0; q < full; q += 4) {
            float wn[8][4];
            if (q + 4 < seg) {
#pragma unroll
                for (int u = 0; u < 4; u++) {
                    int idx = q + 4 + u;
                    if (idx > maxi) idx = maxi;
#pragma unroll
                    for (int j = 0; j < 8; j++) wn[j][u] = __ldg(w + woff[j] + idx);
                }
            }
#pragma unroll
            for (int u = 0; u < 4; u++) {
                const ulonglong2* xp = xs2 + (size_t)(c0 + q + u) * 64;
                ulonglong2 xv0 = xp[l0];
                ulonglong2 xv1 = xp[l1];
#pragma unroll
                for (int j = 0; j < 8; j++) {
                    unsigned long long w2 = pack2(wc[j][u]);
                    fma2(acc[j][0], w2, xv0.x);
                    fma2(acc[j][1], w2, xv0.y);
                    fma2(acc[j][2], w2, xv1.x);
                    fma2(acc[j][3], w2, xv1.y);
                }
            }
            if (q + 4 < seg) {
#pragma unroll
                for (int u = 0; u < 4; u++)
#pragma unroll
                    for (int j = 0; j < 8; j++) wc[j][u] = wn[j][u];
            }
        }
        // tail (< 4 iters), static indices into wc
#pragma unroll
        for (int u = 0; u < 4; u++) {
            if (full + u < seg) {
                const ulonglong2* xp = xs2 + (size_t)(c0 + full + u) * 64;
                ulonglong2 xv0 = xp[l0];
                ulonglong2 xv1 = xp[l1];
#pragma unroll
                for (int j = 0; j < 8; j++) {
                    unsigned long long w2 = pack2(wc[j][u]);
                    fma2(acc[j][0], w2, xv0.x);
                    fma2(acc[j][1], w2, xv0.y);
                    fma2(acc[j][2], w2, xv1.x);
                    fma2(acc[j][3], w2, xv1.y);
                }
            }
        }

        // epilogue: out += (x_a * x_b) * s_ab  (linearity allows partial c-runs)
        {
            const ulonglong2* xbp = xs2 + (size_t)b * 64;
            ulonglong2 xb0 = xbp[l0];
            ulonglong2 xb1 = xbp[l1];
#pragma unroll
            for (int j = 0; j < 8; j++) {
                if (j < na) {
                    const ulonglong2* xap = xs2 + (size_t)(a0 + j) * 64;
                    ulonglong2 xa0 = xap[l0];
                    ulonglong2 xa1 = xap[l1];
                    fma2(ov0, mul2(xa0.x, xb0.x), acc[j][0]);
                    fma2(ov1, mul2(xa0.y, xb0.y), acc[j][1]);
                    fma2(ov2, mul2(xa1.x, xb1.x), acc[j][2]);
                    fma2(ov3, mul2(xa1.y, xb1.y), acc[j][3]);
                }
            }
        }

        pos += seg;
        coff += seg;
        if (coff == L) {
            coff = 0;
            o++;
            if ((o << 3) > b) { o = 0; b++; }
        }
    }

    // ---- per-warp partials -> smem, block combine -> global partial ----
    {
        float4* ob = (float4*)(obuf + warp * NROW);
        union { unsigned long long q[2]; float4 f; } u;
        u.q[0] = ov0; u.q[1] = ov1;
        ob[lane] = u.f;           // rows 4*lane .. 4*lane+3
        u.q[0] = ov2; u.q[1] = ov3;
        ob[lane + 32] = u.f;      // rows 128+4*lane ..
    }
    __syncthreads();
    {
        float ssum = 0.0f;
#pragma unroll
        for (int i = 0; i < WPB; i++) ssum += obuf[i * NROW + tid];
        g_partial[blockIdx.x * NROW + tid] = ssum;
    }

    // ---- fused cross-block reduction: last block to arrive reduces ----
    __shared__ int is_last;
    __threadfence();
    __syncthreads();
    if (tid == 0) is_last = (atomicAdd(&g_count, 1) == NBLK - 1);
    __syncthreads();
    if (is_last) {
        __threadfence();
        float s0 = 0.f, s1 = 0.f, s2 = 0.f, s3 = 0.f;
#pragma unroll
        for (int i = 0; i < NBLK; i += 4) {
            s0 += g_partial[(i + 0) * NROW + tid];
            s1 += g_partial[(i + 1) * NROW + tid];
            s2 += g_partial[(i + 2) * NROW + tid];
            s3 += g_partial[(i + 3) * NROW + tid];
        }
        out[tid] = (s0 + s1) + (s2 + s3);
        if (tid == 0) g_count = 0;  // reset for next graph replay
    }
}

extern "C" void kernel_launch(void* const* d_in, const int* in_sizes, int n_in,
                              void* d_out, int out_size) {
    (void)in_sizes; (void)n_in; (void)out_size;
    const float* x = (const float*)d_in[0];
    const float* w = (const float*)d_in[1];
    // d_in[2] (comb_idx) intentionally unused: lexicographic rank is closed-form.

    size_t smem_bytes = (size_t)(NFEAT * NROW + WPB * NROW) * sizeof(float);  // 140,288 B
    cudaFuncSetAttribute(honu_main, cudaFuncAttributeMaxDynamicSharedMemorySize,
                         (int)smem_bytes);
    honu_main<<<NBLK, 256, smem_bytes>>>(x, w, (float*)d_out);
}

// round 6
// speedup vs baseline: 1.3109x; 1.2557x over previous
#include <cuda_runtime.h>

// HONU degree-3: out[r] = sum_{a<=b<=c} w(a,b,c) * xs[a][r]*xs[b][r]*xs[c][r]
// xs[0][r] = 1 (bias), xs[f][r] = x[r][f-1].
// Weight index of combo (a,b,c) = lexicographic rank (closed form); comb_idx
// input is redundant and ignored.
//
// Pair factorization: for fixed (a,b), the c-run weights are contiguous:
//   s_ab[r] = sum_c w[base(a,b)+(c-b)] * xs[c][r];  out[r] += xs[a][r]*xs[b][r]*s_ab[r]
// 8 consecutive 'a' streams share each xs[c] load; each thread owns 8 rows as
// 4x packed fma.rn.f32x2. 512 threads/block (16 warps -> 4/SMSP for latency
// hiding), regs capped at 128. Weights fetched in chunks of 2 c-steps, no
// prefetch buffer (occupancy hides L2 latency), all loads in-bounds.
// Grid = 148 (1 wave). Cross-block reduction fused via atomic ticket.

#define NFEAT 129
#define NROW  256
#define NBLK  148
#define WPB   16
#define NWORK (NBLK * WPB)   // 2368 workers

__host__ __device__ __forceinline__ int c2i(int v) { return v * (v - 1) / 2; }
__host__ __device__ __forceinline__ int c3i(int v) { return v * (v - 1) * (v - 2) / 6; }

// flat lexicographic rank of combo (a, b, b); total combos = C(131,3) = 366145
__device__ __forceinline__ int comb_base(int a, int b) {
    return 366145 - c3i(131 - a) + c2i(130 - a) - c2i(130 - b);
}

// total blocked c-iterations: sum_b ceil((b+1)/8) * (129-b)
constexpr int blocked_total() {
    int t = 0;
    for (int b = 0; b < NFEAT; b++) t += ((b + 8) / 8) * (NFEAT - b);
    return t;
}
constexpr int T_TOTAL = blocked_total();

__device__ float g_partial[NBLK * NROW];
__device__ int   g_count = 0;

__device__ __forceinline__ unsigned long long pack2(float w) {
    unsigned long long r;
    unsigned int wi = __float_as_uint(w);
    asm("mov.b64 %0, {%1, %1};" : "=l"(r) : "r"(wi));
    return r;
}
__device__ __forceinline__ void fma2(unsigned long long& d, unsigned long long a,
                                     unsigned long long b) {
    asm("fma.rn.f32x2 %0, %1, %2, %0;" : "+l"(d) : "l"(a), "l"(b));
}
__device__ __forceinline__ unsigned long long mul2(unsigned long long a,
                                                   unsigned long long b) {
    unsigned long long d;
    asm("mul.rn.f32x2 %0, %1, %2;" : "=l"(d) : "l"(a), "l"(b));
    return d;
}

__global__ void __launch_bounds__(512, 1)
honu_main(const float* __restrict__ x, const float* __restrict__ w,
          float* __restrict__ out) {
    extern __shared__ float smem[];
    float* xs   = smem;                   // [129][256] feature-major
    float* obuf = smem + NFEAT * NROW;    // [16][256] per-warp partials

    int tid = threadIdx.x;

    // ---- prologue: x transposed into smem (thread t < 256 owns row t) ----
    if (tid < NROW) {
        const float4* xg = (const float4*)(x + (size_t)tid * 128);
#pragma unroll
        for (int k = 0; k < 32; k++) {
            float4 v = xg[k];
            xs[(4 * k + 1) * NROW + tid] = v.x;
            xs[(4 * k + 2) * NROW + tid] = v.y;
            xs[(4 * k + 3) * NROW + tid] = v.z;
            xs[(4 * k + 4) * NROW + tid] = v.w;
        }
        xs[tid] = 1.0f;  // bias feature
    }
    __syncthreads();

    int warp = tid >> 5, lane = tid & 31;
    int worker = blockIdx.x * WPB + warp;

    int s = (int)(((long long)T_TOTAL * worker) / NWORK);
    int e = (int)(((long long)T_TOTAL * (worker + 1)) / NWORK);

    // decode start -> (b, octet o, c-offset)
    int b = 0, pref = 0;
    for (;;) {
        int nb = pref + ((b + 8) >> 3) * (NFEAT - b);
        if (nb > s) break;
        pref = nb;
        b++;
    }
    int L = NFEAT - b;
    int rem = s - pref;
    int o = rem / L;
    int coff = rem % L;
    int pos = s;

    unsigned long long ov0 = 0, ov1 = 0, ov2 = 0, ov3 = 0;  // 8 rows as 4x f32x2

    const ulonglong2* xs2 = (const ulonglong2*)xs;  // 64 16B-quads per feature
    const int l0 = lane, l1 = lane + 32;

    while (pos < e) {
        L = NFEAT - b;
        int a0 = o << 3;
        int na = b + 1 - a0;
        if (na > 8) na = 8;
        int seg = L - coff;
        if (seg > e - pos) seg = e - pos;

        const float* wp[8];
#pragma unroll
        for (int j = 0; j < 8; j++)
            wp[j] = w + ((j < na) ? (comb_base(a0 + j, b) + coff) : 0);

        const ulonglong2* xp = xs2 + (size_t)(b + coff) * 64;

        unsigned long long acc[8][4];
#pragma unroll
        for (int j = 0; j < 8; j++) {
            acc[j][0] = 0; acc[j][1] = 0; acc[j][2] = 0; acc[j][3] = 0;
        }

        // ---- c loop: chunks of 2 steps, loads always in-bounds ----
        int q = 0;
        for (; q + 2 <= seg; q += 2) {
            float wc[8][2];
#pragma unroll
            for (int j = 0; j < 8; j++) {
                wc[j][0] = __ldg(wp[j] + q);
                wc[j][1] = __ldg(wp[j] + q + 1);
            }
#pragma unroll
            for (int u = 0; u < 2; u++) {
                const ulonglong2* xq = xp + (size_t)(q + u) * 64;
                ulonglong2 xv0 = xq[l0];
                ulonglong2 xv1 = xq[l1];
#pragma unroll
                for (int j = 0; j < 8; j++) {
                    unsigned long long w2 = pack2(wc[j][u]);
                    fma2(acc[j][0], w2, xv0.x);
                    fma2(acc[j][1], w2, xv0.y);
                    fma2(acc[j][2], w2, xv1.x);
                    fma2(acc[j][3], w2, xv1.y);
                }
            }
        }
        if (q < seg) {  // tail step
            const ulonglong2* xq = xp + (size_t)q * 64;
            ulonglong2 xv0 = xq[l0];
            ulonglong2 xv1 = xq[l1];
#pragma unroll
            for (int j = 0; j < 8; j++) {
                unsigned long long w2 = pack2(__ldg(wp[j] + q));
                fma2(acc[j][0], w2, xv0.x);
                fma2(acc[j][1], w2, xv0.y);
                fma2(acc[j][2], w2, xv1.x);
                fma2(acc[j][3], w2, xv1.y);
            }
        }

        // epilogue: out += (x_a * x_b) * s_ab  (linearity allows partial c-runs)
        {
            const ulonglong2* xbp = xs2 + (size_t)b * 64;
            ulonglong2 xb0 = xbp[l0];
            ulonglong2 xb1 = xbp[l1];
#pragma unroll
            for (int j = 0; j < 8; j++) {
                if (j < na) {
                    const ulonglong2* xap = xs2 + (size_t)(a0 + j) * 64;
                    ulonglong2 xa0 = xap[l0];
                    ulonglong2 xa1 = xap[l1];
                    fma2(ov0, mul2(xa0.x, xb0.x), acc[j][0]);
                    fma2(ov1, mul2(xa0.y, xb0.y), acc[j][1]);
                    fma2(ov2, mul2(xa1.x, xb1.x), acc[j][2]);
                    fma2(ov3, mul2(xa1.y, xb1.y), acc[j][3]);
                }
            }
        }

        pos += seg;
        coff += seg;
        if (coff == L) {
            coff = 0;
            o++;
            if ((o << 3) > b) { o = 0; b++; }
        }
    }

    // ---- per-warp partials -> smem, block combine -> global partial ----
    {
        float4* ob = (float4*)(obuf + warp * NROW);
        union { unsigned long long q[2]; float4 f; } u;
        u.q[0] = ov0; u.q[1] = ov1;
        ob[lane] = u.f;           // rows 4*lane .. 4*lane+3
        u.q[0] = ov2; u.q[1] = ov3;
        ob[lane + 32] = u.f;      // rows 128+4*lane ..
    }
    __syncthreads();
    if (tid < NROW) {
        float ssum = 0.0f;
#pragma unroll
        for (int i = 0; i < WPB; i++) ssum += obuf[i * NROW + tid];
        g_partial[blockIdx.x * NROW + tid] = ssum;
    }

    // ---- fused cross-block reduction: last block to arrive reduces ----
    __shared__ int is_last;
    __threadfence();
    __syncthreads();
    if (tid == 0) is_last = (atomicAdd(&g_count, 1) == NBLK - 1);
    __syncthreads();
    if (is_last && tid < NROW) {
        __threadfence();
        float s0 = 0.f, s1 = 0.f, s2 = 0.f, s3 = 0.f;
#pragma unroll
        for (int i = 0; i < NBLK; i += 4) {
            s0 += g_partial[(i + 0) * NROW + tid];
            s1 += g_partial[(i + 1) * NROW + tid];
            s2 += g_partial[(i + 2) * NROW + tid];
            s3 += g_partial[(i + 3) * NROW + tid];
        }
        out[tid] = (s0 + s1) + (s2 + s3);
        if (tid == 0) g_count = 0;  // reset for next graph replay
    }
}

extern "C" void kernel_launch(void* const* d_in, const int* in_sizes, int n_in,
                              void* d_out, int out_size) {
    (void)in_sizes; (void)n_in; (void)out_size;
    const float* x = (const float*)d_in[0];
    const float* w = (const float*)d_in[1];
    // d_in[2] (comb_idx) intentionally unused: lexicographic rank is closed-form.

    size_t smem_bytes = (size_t)(NFEAT * NROW + WPB * NROW) * sizeof(float);  // 148,480 B
    cudaFuncSetAttribute(honu_main, cudaFuncAttributeMaxDynamicSharedMemorySize,
                         (int)smem_bytes);
    honu_main<<<NBLK, 512, smem_bytes>>>(x, w, (float*)d_out);
}

// round 7
// speedup vs baseline: 1.3733x; 1.0476x over previous
#include <cuda_runtime.h>

// HONU degree-3: out[r] = sum_{a<=b<=c} w(a,b,c) * xs[a][r]*xs[b][r]*xs[c][r]
// xs[0][r] = 1 (bias), xs[f][r] = x[r][f-1].
// Weight index of combo (a,b,c) = lexicographic rank (closed form); comb_idx
// input is redundant and ignored.
//
// Pair factorization: for fixed (a,b), the c-run weights are contiguous:
//   s_ab[r] = sum_c w[base(a,b)+(c-b)] * xs[c][r];  out[r] += xs[a][r]*xs[b][r]*s_ab[r]
// 8 consecutive 'a' streams share each xs[c] load. Each thread owns 4 rows
// (2x packed fma.rn.f32x2): a warp covers one 128-row half, warp pairs share a
// (b,octet,c) range. This halves per-thread accumulator state vs R6 (which
// spilled at the 128-reg cap) and leaves room for a 1-chunk weight prefetch.
// Worker start decoded by binary search on closed-form pref8(b).
// Grid = 148 (1 wave). Cross-block reduction fused via atomic ticket.

#define NFEAT 129
#define NROW  256
#define NBLK  148
#define WPB   16
#define NRANGE (NBLK * WPB / 2)   // 1184 ranges (2 warps each: row halves)

__host__ __device__ __forceinline__ int c2i(int v) { return v * (v - 1) / 2; }
__host__ __device__ __forceinline__ int c3i(int v) { return v * (v - 1) * (v - 2) / 6; }

// flat lexicographic rank of combo (a, b, b); total combos = C(131,3) = 366145
__device__ __forceinline__ int comb_base(int a, int b) {
    return 366145 - c3i(131 - a) + c2i(130 - a) - c2i(130 - b);
}

// prefix of blocked c-steps before feature b: sum_{b'<b} (floor(b'/8)+1)*(129-b')
__host__ __device__ constexpr int pref8(int b) {
    int T = b >> 3, r = b & 7;
    int S = 129 * b - (b * (b - 1)) / 2;
    int Q = 502 * T * (T - 1) - 64 * (((T - 1) * T * (2 * T - 1)) / 6)
          + T * (r * (129 - 8 * T) - (r * (r - 1)) / 2);
    return S + Q;
}

constexpr int blocked_total() {
    int t = 0;
    for (int b = 0; b < NFEAT; b++) t += ((b + 8) / 8) * (NFEAT - b);
    return t;
}
constexpr int T_TOTAL = blocked_total();
static_assert(pref8(NFEAT) == T_TOTAL, "pref8 closed form mismatch");
static_assert(pref8(8) == 1004 && pref8(9) == 1246, "pref8 spot check");

__device__ float g_partial[NBLK * NROW];
__device__ int   g_count = 0;

__device__ __forceinline__ unsigned long long pack2(float w) {
    unsigned long long r;
    unsigned int wi = __float_as_uint(w);
    asm("mov.b64 %0, {%1, %1};" : "=l"(r) : "r"(wi));
    return r;
}
__device__ __forceinline__ void fma2(unsigned long long& d, unsigned long long a,
                                     unsigned long long b) {
    asm("fma.rn.f32x2 %0, %1, %2, %0;" : "+l"(d) : "l"(a), "l"(b));
}
__device__ __forceinline__ unsigned long long mul2(unsigned long long a,
                                                   unsigned long long b) {
    unsigned long long d;
    asm("mul.rn.f32x2 %0, %1, %2;" : "=l"(d) : "l"(a), "l"(b));
    return d;
}

__global__ void __launch_bounds__(512, 1)
honu_main(const float* __restrict__ x, const float* __restrict__ w,
          float* __restrict__ out) {
    extern __shared__ float smem[];
    float* xs   = smem;                   // [129][256] feature-major
    float* obuf = smem + NFEAT * NROW;    // [16][128] per-warp half-row partials

    int tid = threadIdx.x;

    // ---- prologue: x transposed into smem, all 512 threads ----
    {
        int r = tid & 255, h = tid >> 8;            // h = which 64-feature half
        const float4* xg = (const float4*)(x + (size_t)r * 128 + h * 64);
#pragma unroll
        for (int k = 0; k < 16; k++) {
            float4 v = xg[k];
            int f = h * 64 + 4 * k;
            xs[(f + 1) * NROW + r] = v.x;
            xs[(f + 2) * NROW + r] = v.y;
            xs[(f + 3) * NROW + r] = v.z;
            xs[(f + 4) * NROW + r] = v.w;
        }
        if (h == 0) xs[r] = 1.0f;  // bias feature
    }
    __syncthreads();

    int warp = tid >> 5, lane = tid & 31;
    int worker = blockIdx.x * WPB + warp;
    int range = worker >> 1;
    int rh    = worker & 1;             // row half: 0 -> rows 0-127, 1 -> 128-255

    int s = (int)(((long long)T_TOTAL * range) / NRANGE);
    int e = (int)(((long long)T_TOTAL * (range + 1)) / NRANGE);

    // ---- decode start -> (b, octet o, c-offset) via binary search ----
    int lo = 0, hi = NFEAT - 1;
    while (lo < hi) {                   // largest b with pref8(b) <= s
        int mid = (lo + hi + 1) >> 1;
        if (pref8(mid) <= s) lo = mid; else hi = mid - 1;
    }
    int b = lo;
    int L = NFEAT - b;
    int rem = s - pref8(b);
    int o = rem / L;
    int coff = rem % L;
    int pos = s;

    unsigned long long ov0 = 0, ov1 = 0;          // 4 rows as 2x f32x2

    const ulonglong2* xs2 = (const ulonglong2*)xs;  // 64 16B-quads per feature
    const int lq = rh * 32 + lane;                  // this thread's quad index

    while (pos < e) {
        L = NFEAT - b;
        int a0 = o << 3;
        int na = b + 1 - a0;
        if (na > 8) na = 8;
        int seg = L - coff;
        if (seg > e - pos) seg = e - pos;

        unsigned int woff[8];
#pragma unroll
        for (int j = 0; j < 8; j++)
            woff[j] = (unsigned int)((j < na) ? (comb_base(a0 + j, b) + coff) : 0);

        const ulonglong2* xp = xs2 + (size_t)(b + coff) * 64 + lq;

        unsigned long long acc[8][2];
#pragma unroll
        for (int j = 0; j < 8; j++) { acc[j][0] = 0; acc[j][1] = 0; }

        // ---- c loop: pairs of steps, 1-chunk weight prefetch ----
        float wc[8][2];
        if (seg >= 2) {
#pragma unroll
            for (int j = 0; j < 8; j++) {
                wc[j][0] = __ldg(w + woff[j]);
                wc[j][1] = __ldg(w + woff[j] + 1);
            }
        }
        int q = 0;
        for (; q + 2 <= seg; q += 2) {
            float wn[8][2];
            bool pf = (q + 4 <= seg);
            if (pf) {
#pragma unroll
                for (int j = 0; j < 8; j++) {
                    wn[j][0] = __ldg(w + woff[j] + q + 2);
                    wn[j][1] = __ldg(w + woff[j] + q + 3);
                }
            }
#pragma unroll
            for (int u = 0; u < 2; u++) {
                ulonglong2 xv = xp[(size_t)(q + u) * 64];
#pragma unroll
                for (int j = 0; j < 8; j++) {
                    unsigned long long w2 = pack2(wc[j][u]);
                    fma2(acc[j][0], w2, xv.x);
                    fma2(acc[j][1], w2, xv.y);
                }
            }
            if (pf) {
#pragma unroll
                for (int j = 0; j < 8; j++) { wc[j][0] = wn[j][0]; wc[j][1] = wn[j][1]; }
            }
        }
        if (q < seg) {  // odd tail step
            ulonglong2 xv = xp[(size_t)q * 64];
#pragma unroll
            for (int j = 0; j < 8; j++) {
                unsigned long long w2 = pack2(__ldg(w + woff[j] + q));
                fma2(acc[j][0], w2, xv.x);
                fma2(acc[j][1], w2, xv.y);
            }
        }

        // epilogue: out += (x_a * x_b) * s_ab  (linearity allows partial c-runs)
        {
            ulonglong2 xb = xs2[(size_t)b * 64 + lq];
#pragma unroll
            for (int j = 0; j < 8; j++) {
                if (j < na) {
                    ulonglong2 xa = xs2[(size_t)(a0 + j) * 64 + lq];
                    fma2(ov0, mul2(xa.x, xb.x), acc[j][0]);
                    fma2(ov1, mul2(xa.y, xb.y), acc[j][1]);
                }
            }
        }

        pos += seg;
        coff += seg;
        if (coff == L) {
            coff = 0;
            o++;
            if ((o << 3) > b) { o = 0; b++; }
        }
    }

    // ---- per-warp half-row partials -> smem, block combine -> global ----
    {
        float4* ob = (float4*)(obuf + warp * 128);
        union { unsigned long long q[2]; float4 f; } u;
        u.q[0] = ov0; u.q[1] = ov1;
        ob[lane] = u.f;                 // rows rh*128 + 4*lane .. +3
    }
    __syncthreads();
    if (tid < NROW) {
        int trh = tid >> 7, rr = tid & 127;
        float ssum = 0.0f;
#pragma unroll
        for (int k = 0; k < 8; k++) ssum += obuf[(2 * k + trh) * 128 + rr];
        g_partial[blockIdx.x * NROW + tid] = ssum;
    }

    // ---- fused cross-block reduction: last block to arrive reduces ----
    __shared__ int is_last;
    __threadfence();
    __syncthreads();
    if (tid == 0) is_last = (atomicAdd(&g_count, 1) == NBLK - 1);
    __syncthreads();
    if (is_last && tid < NROW) {
        __threadfence();
        float s0 = 0.f, s1 = 0.f, s2 = 0.f, s3 = 0.f;
#pragma unroll
        for (int i = 0; i < NBLK; i += 4) {
            s0 += g_partial[(i + 0) * NROW + tid];
            s1 += g_partial[(i + 1) * NROW + tid];
            s2 += g_partial[(i + 2) * NROW + tid];
            s3 += g_partial[(i + 3) * NROW + tid];
        }
        out[tid] = (s0 + s1) + (s2 + s3);
        if (tid == 0) g_count = 0;  // reset for next graph replay
    }
}

extern "C" void kernel_launch(void* const* d_in, const int* in_sizes, int n_in,
                              void* d_out, int out_size) {
    (void)in_sizes; (void)n_in; (void)out_size;
    const float* x = (const float*)d_in[0];
    const float* w = (const float*)d_in[1];
    // d_in[2] (comb_idx) intentionally unused: lexicographic rank is closed-form.

    size_t smem_bytes = (size_t)(NFEAT * NROW + WPB * 128) * sizeof(float);  // 140,288 B
    cudaFuncSetAttribute(honu_main, cudaFuncAttributeMaxDynamicSharedMemorySize,
                         (int)smem_bytes);
    honu_main<<<NBLK, 512, smem_bytes>>>(x, w, (float*)d_out);
}